// round 7
// baseline (speedup 1.0000x reference)
#include <cuda_runtime.h>
#include <mma.h>
#include <cstdint>
#include <cstddef>

using namespace nvcuda;

#define NN 10000
#define NE 320000
#define FD 256
#define EDF 64

// weight offsets inside g_wr
#define OW1 0
#define OM1 (FD * FD)
#define OM2 (OM1 + 576 * FD)
#define OW2 (OM2 + 576 * FD)
#define WTOT (OW2 + FD * FD)

// ---------------- scratch ----------------
__device__ float g_h0[NN * FD];
__device__ float g_h1[NN * FD];
__device__ float g_Xs[NN * FD];
__device__ float g_Xd[NN * FD];
__device__ float g_xr[NN * FD];
__device__ float g_efr[(size_t)NE * EDF];
__device__ float g_wr[WTOT];
__device__ int g_rowptr[NN + 1];
__device__ int g_cnt[NN];
__device__ int g_ofs[NN];
__device__ int g_srcs[NE];
__device__ int g_dsts[NE];
__device__ int g_eids[NE];

__device__ __forceinline__ float gelu_f(float v) {
    float u = 0.7978845608028654f * (v + 0.044715f * v * v * v);
    float t;
    asm("tanh.approx.f32 %0, %1;" : "=f"(t) : "f"(u));
    return 0.5f * v * (1.0f + t);
}

__device__ __forceinline__ void cp16(uint32_t dst, const void* src, bool p) {
    asm volatile("cp.async.ca.shared.global [%0], [%1], 16, %2;"
                 :: "r"(dst), "l"(src), "r"(p ? 16 : 0));
}
#define CP_COMMIT() asm volatile("cp.async.commit_group;")
#define CP_WAIT(n)  asm volatile("cp.async.wait_group %0;" :: "n"(n))

// ---------------- tf32 pre-round: x, ef, all weights in ONE launch ----------------
__global__ void round_all(const float* __restrict__ x, const float* __restrict__ ef,
                          const float* __restrict__ wff1, const float* __restrict__ wmp1,
                          const float* __restrict__ wmp2, const float* __restrict__ wff2,
                          float* __restrict__ xr, float* __restrict__ efr,
                          float* __restrict__ wr) {
    const int NX4 = NN * FD / 4;
    const int NE4 = NE * EDF / 4;
    const int W14 = FD * FD / 4, WM4 = 576 * FD / 4;
    long long i = (long long)blockIdx.x * blockDim.x + threadIdx.x;
    const float4* s;
    float4* d;
    long long j = i;
    if (j < NX4) { s = (const float4*)x; d = (float4*)xr; }
    else {
        j -= NX4;
        if (j < NE4) { s = (const float4*)ef; d = (float4*)efr; }
        else {
            j -= NE4;
            if (j < W14) { s = (const float4*)wff1; d = (float4*)(wr + OW1); }
            else {
                j -= W14;
                if (j < WM4) { s = (const float4*)wmp1; d = (float4*)(wr + OM1); }
                else {
                    j -= WM4;
                    if (j < WM4) { s = (const float4*)wmp2; d = (float4*)(wr + OM2); }
                    else {
                        j -= WM4;
                        if (j >= W14) return;
                        s = (const float4*)wff2; d = (float4*)(wr + OW2);
                    }
                }
            }
        }
    }
    float4 v = s[j];
    v.x = wmma::__float_to_tf32(v.x);
    v.y = wmma::__float_to_tf32(v.y);
    v.z = wmma::__float_to_tf32(v.z);
    v.w = wmma::__float_to_tf32(v.w);
    d[j] = v;
}

// ---------------- CSR construction ----------------
__global__ void zero_kernel(int* __restrict__ p, int n) {
    int i = blockIdx.x * blockDim.x + threadIdx.x;
    if (i < n) p[i] = 0;
}

__global__ void hist_kernel(const int* __restrict__ ei, int* __restrict__ cnt, int E) {
    int e = blockIdx.x * blockDim.x + threadIdx.x;
    if (e < E) atomicAdd(&cnt[ei[E + e]], 1);
}

__global__ void scan_kernel(const int* __restrict__ cnt, int* __restrict__ rowptr,
                            int* __restrict__ ofs, int n) {
    __shared__ int part[1024];
    const int PER = 16;
    int t = threadIdx.x;
    int base = t * PER;
    int local[PER];
    int s = 0;
#pragma unroll
    for (int j = 0; j < PER; j++) {
        int idx = base + j;
        int c = (idx < n) ? cnt[idx] : 0;
        local[j] = s;
        s += c;
    }
    part[t] = s;
    __syncthreads();
    for (int off = 1; off < 1024; off <<= 1) {
        int v = (t >= off) ? part[t - off] : 0;
        __syncthreads();
        part[t] += v;
        __syncthreads();
    }
    int pre = (t > 0) ? part[t - 1] : 0;
#pragma unroll
    for (int j = 0; j < PER; j++) {
        int idx = base + j;
        if (idx < n) {
            int v = pre + local[j];
            rowptr[idx] = v;
            ofs[idx] = v;
        }
    }
    if (t == 1023) rowptr[n] = part[1023];
}

__global__ void scatter_kernel(const int* __restrict__ ei, int* __restrict__ ofs,
                               int* __restrict__ srcs, int* __restrict__ dsts,
                               int* __restrict__ eids, int E) {
    int e = blockIdx.x * blockDim.x + threadIdx.x;
    if (e < E) {
        int d = ei[E + e];
        int p = atomicAdd(&ofs[d], 1);
        srcs[p] = ei[e];
        dsts[p] = d;
        eids[p] = e;
    }
}

__global__ void copy_kernel(const float4* __restrict__ a, float4* __restrict__ b, int n4) {
    int i = blockIdx.x * blockDim.x + threadIdx.x;
    if (i < n4) b[i] = a[i];
}

// ---------------- node GEMM: cp.async 2-stage, cvt-free when inputs pre-rounded ----------------
template <int CVT_A>
__global__ void __launch_bounds__(256) gemm_node(
    const float* __restrict__ A,
    const float* __restrict__ B0, const float* __restrict__ B1,
    const float* __restrict__ bias,
    const float* __restrict__ resid,
    float* __restrict__ C0, float* __restrict__ C1,
    int M, int dogelu, int roundout)
{
    constexpr int BM = 128, BN = 64, BK = 32;
    constexpr int LDA = 36, LDB = 68;
    constexpr int STG = BM * LDA + BK * LDB;
    __shared__ __align__(16) float sm[2 * STG];
    float* Cs = sm;

    int tid = threadIdx.x;
    int warp = tid >> 5;
    int wm = warp >> 1, wn = warp & 1;
    int bm = blockIdx.x * BM;
    int sel = blockIdx.y >> 2;
    int cg = blockIdx.y & 3;
    const float* B = sel ? B1 : B0;
    float* C = sel ? C1 : C0;
    int bn = cg * BN;

    int lra = tid >> 3, lca = (tid & 7) << 2;
    int lrb = tid >> 4, lcb = (tid & 15) << 2;

    auto issue = [&](int st, int k0) {
        float* As = sm + st * STG;
        float* Bs = As + BM * LDA;
#pragma unroll
        for (int p = 0; p < 4; p++) {
            int row = lra + 32 * p;
            int grow = bm + row;
            cp16((uint32_t)__cvta_generic_to_shared(As + row * LDA + lca),
                 A + (size_t)grow * FD + k0 + lca, grow < M);
        }
#pragma unroll
        for (int p = 0; p < 2; p++) {
            int row = lrb + 16 * p;
            cp16((uint32_t)__cvta_generic_to_shared(Bs + row * LDB + lcb),
                 B + (size_t)(k0 + row) * FD + bn + lcb, true);
        }
    };

    wmma::fragment<wmma::accumulator, 16, 16, 8, float> acc[2][2];
#pragma unroll
    for (int i = 0; i < 2; i++)
#pragma unroll
        for (int j = 0; j < 2; j++) wmma::fill_fragment(acc[i][j], 0.0f);

    issue(0, 0);
    CP_COMMIT();

    constexpr int NIT = FD / BK;  // 8
#pragma unroll 1
    for (int it = 0; it < NIT; it++) {
        if (it + 1 < NIT) {
            issue((it + 1) & 1, (it + 1) * BK);
            CP_COMMIT();
            CP_WAIT(1);
        } else {
            CP_WAIT(0);
        }
        __syncthreads();
        float* As = sm + (it & 1) * STG;
        float* Bs = As + BM * LDA;
#pragma unroll
        for (int kk = 0; kk < BK; kk += 8) {
            wmma::fragment<wmma::matrix_a, 16, 16, 8, wmma::precision::tf32, wmma::row_major> a[2];
            wmma::fragment<wmma::matrix_b, 16, 16, 8, wmma::precision::tf32, wmma::row_major> b[2];
#pragma unroll
            for (int i = 0; i < 2; i++) {
                wmma::load_matrix_sync(a[i], As + (wm * 32 + i * 16) * LDA + kk, LDA);
                if (CVT_A) {
#pragma unroll
                    for (int e = 0; e < a[i].num_elements; e++)
                        a[i].x[e] = wmma::__float_to_tf32(a[i].x[e]);
                }
            }
#pragma unroll
            for (int j = 0; j < 2; j++)
                wmma::load_matrix_sync(b[j], Bs + kk * LDB + wn * 32 + j * 16, LDB);
#pragma unroll
            for (int i = 0; i < 2; i++)
#pragma unroll
                for (int j = 0; j < 2; j++)
                    wmma::mma_sync(acc[i][j], a[i], b[j], acc[i][j]);
        }
        __syncthreads();
    }

#pragma unroll
    for (int i = 0; i < 2; i++)
#pragma unroll
        for (int j = 0; j < 2; j++)
            wmma::store_matrix_sync(Cs + (wm * 32 + i * 16) * BN + wn * 32 + j * 16,
                                    acc[i][j], BN, wmma::mem_row_major);
    __syncthreads();
    for (int idx = tid; idx < BM * BN; idx += 256) {
        int r = idx >> 6, c = idx & 63;
        int grow = bm + r;
        if (grow >= M) continue;
        float v = Cs[idx];
        if (bias) v += bias[bn + c];
        if (dogelu) v = gelu_f(v);
        if (roundout) v = wmma::__float_to_tf32(v);
        if (resid) v += resid[(size_t)grow * FD + bn + c];
        C[(size_t)grow * FD + bn + c] = v;
    }
}

// ---------------- fused edge kernel (cvt-free: efr + wr pre-rounded) ----------------
__global__ void __launch_bounds__(256) edge_fused(
    const float* __restrict__ ef,    // tf32-rounded
    const float* __restrict__ Wef,   // [64, 256] tf32-rounded
    const float* __restrict__ bias,
    const float* __restrict__ Xs, const float* __restrict__ Xd,
    float* __restrict__ out,         // pre-seeded with hin
    int E)
{
    constexpr int CH = 128, LDA = 68, LDB = 68;
    __shared__ __align__(16) float Aef[CH * LDA];
    __shared__ __align__(16) float CsWb[CH * LDA];
    __shared__ int s_src[CH], s_dst[CH], s_eid[CH];

    int tid = threadIdx.x;
    int base = blockIdx.x * CH;
    int warp = tid >> 5;
    int wm = warp >> 1, wn = warp & 1;

    if (tid < CH) {
        int i = base + tid;
        bool v = i < E;
        s_eid[tid] = v ? g_eids[i] : 0;
        s_src[tid] = v ? g_srcs[i] : 0;
        s_dst[tid] = v ? g_dsts[i] : -1;
    }
    __syncthreads();

#pragma unroll
    for (int p = 0; p < 8; p++) {
        int j = tid + 256 * p;
        int row = j >> 4;
        int c4 = j & 15;
        float4 v = make_float4(0.f, 0.f, 0.f, 0.f);
        if (base + row < E)
            v = ((const float4*)(ef + (size_t)s_eid[row] * EDF))[c4];
        *(float4*)(Aef + row * LDA + c4 * 4) = v;
    }
    __syncthreads();

    int c = tid & 63;
    int q = tid >> 6;

#pragma unroll 1
    for (int cgi = 0; cgi < 2; cgi++) {
        int cg = blockIdx.y * 2 + cgi;
        float* Wb = CsWb;
#pragma unroll
        for (int p = 0; p < 4; p++) {
            int j = tid + 256 * p;
            int row = j >> 4;
            int c4 = j & 15;
            *(float4*)(Wb + row * LDB + c4 * 4) =
                *(const float4*)(Wef + (size_t)row * FD + cg * 64 + c4 * 4);
        }
        __syncthreads();

        wmma::fragment<wmma::accumulator, 16, 16, 8, float> acc[2][2];
#pragma unroll
        for (int i = 0; i < 2; i++)
#pragma unroll
            for (int j = 0; j < 2; j++) wmma::fill_fragment(acc[i][j], 0.0f);

#pragma unroll
        for (int kk = 0; kk < EDF; kk += 8) {
            wmma::fragment<wmma::matrix_a, 16, 16, 8, wmma::precision::tf32, wmma::row_major> a[2];
            wmma::fragment<wmma::matrix_b, 16, 16, 8, wmma::precision::tf32, wmma::row_major> b[2];
#pragma unroll
            for (int i = 0; i < 2; i++)
                wmma::load_matrix_sync(a[i], Aef + (wm * 32 + i * 16) * LDA + kk, LDA);
#pragma unroll
            for (int j = 0; j < 2; j++)
                wmma::load_matrix_sync(b[j], Wb + kk * LDB + wn * 32 + j * 16, LDB);
#pragma unroll
            for (int i = 0; i < 2; i++)
#pragma unroll
                for (int j = 0; j < 2; j++)
                    wmma::mma_sync(acc[i][j], a[i], b[j], acc[i][j]);
        }
        __syncthreads();

        float* Cs = CsWb;
#pragma unroll
        for (int i = 0; i < 2; i++)
#pragma unroll
            for (int j = 0; j < 2; j++)
                wmma::store_matrix_sync(Cs + (wm * 32 + i * 16) * LDA + wn * 32 + j * 16,
                                        acc[i][j], LDA, wmma::mem_row_major);
        __syncthreads();

        float bv = bias[cg * 64 + c];
        float accv = 0.0f, xdv = 0.0f;
        int prev = -2;
#pragma unroll
        for (int r0 = 0; r0 < 32; r0 += 8) {
            float xs[8];
#pragma unroll
            for (int r = 0; r < 8; r++) {
                int row = q * 32 + r0 + r;
                xs[r] = (base + row < E)
                      ? Xs[(size_t)s_src[row] * FD + cg * 64 + c] : 0.0f;
            }
#pragma unroll
            for (int r = 0; r < 8; r++) {
                int row = q * 32 + r0 + r;
                if (base + row >= E) break;
                int d = s_dst[row];
                if (d != prev) {
                    if (prev >= 0) atomicAdd(&out[(size_t)prev * FD + cg * 64 + c], accv);
                    accv = 0.0f;
                    prev = d;
                    xdv = Xd[(size_t)d * FD + cg * 64 + c];
                }
                accv += gelu_f(Cs[row * LDA + c] + bv + xs[r] + xdv);
            }
        }
        if (prev >= 0) atomicAdd(&out[(size_t)prev * FD + cg * 64 + c], accv);
        __syncthreads();
    }
}

// ---------------- launch ----------------
extern "C" void kernel_launch(void* const* d_in, const int* in_sizes, int n_in,
                              void* d_out, int out_size) {
    const float* x    = (const float*)d_in[0];
    const int* ei     = (const int*)d_in[1];   // int32 (JAX x64 disabled)
    const float* ef   = (const float*)d_in[2];
    const float* Wff1 = (const float*)d_in[3];
    const float* bff1 = (const float*)d_in[4];
    const float* Wmp1 = (const float*)d_in[5];
    const float* bmp1 = (const float*)d_in[6];
    const float* Wmp2 = (const float*)d_in[7];
    const float* bmp2 = (const float*)d_in[8];
    const float* Wff2 = (const float*)d_in[9];
    const float* bff2 = (const float*)d_in[10];

    int N = in_sizes[0] / FD;
    int E = in_sizes[1] / 2;

    float *h0, *h1, *Xs, *Xd, *xr, *efr, *wr;
    int *rowptr, *cnt, *ofs, *srcs, *dsts, *eids;
    cudaGetSymbolAddress((void**)&h0, g_h0);
    cudaGetSymbolAddress((void**)&h1, g_h1);
    cudaGetSymbolAddress((void**)&Xs, g_Xs);
    cudaGetSymbolAddress((void**)&Xd, g_Xd);
    cudaGetSymbolAddress((void**)&xr, g_xr);
    cudaGetSymbolAddress((void**)&efr, g_efr);
    cudaGetSymbolAddress((void**)&wr, g_wr);
    cudaGetSymbolAddress((void**)&rowptr, g_rowptr);
    cudaGetSymbolAddress((void**)&cnt, g_cnt);
    cudaGetSymbolAddress((void**)&ofs, g_ofs);
    cudaGetSymbolAddress((void**)&srcs, g_srcs);
    cudaGetSymbolAddress((void**)&dsts, g_dsts);
    cudaGetSymbolAddress((void**)&eids, g_eids);

    dim3 thr(256);
    int eb = (E + 255) / 256;
    int n4 = N * FD / 4;
    long long tot4 = (long long)N * FD / 4 + (long long)E * EDF / 4 + WTOT / 4;

    dim3 gN((N + 127) / 128, 4);
    dim3 gN2((N + 127) / 128, 8);
    dim3 gE((E + 127) / 128, 2);

    // 1: pre-round everything to tf32
    round_all<<<(int)((tot4 + 255) / 256), thr>>>(x, ef, Wff1, Wmp1, Wmp2, Wff2, xr, efr, wr);
    // 2-4: zero, FFN1, dual1 (slot 4 = ncu probe)
    zero_kernel<<<(N + 255) / 256, thr>>>(cnt, N);
    gemm_node<0><<<gN, thr>>>(xr, wr + OW1, nullptr, bff1, nullptr, h0, nullptr, N, 1, 1);
    gemm_node<0><<<gN2, thr>>>(h0, wr + OM1, wr + OM1 + FD * FD, nullptr, nullptr, Xs, Xd, N, 0, 0);  // PROBE
    // 5-7: CSR
    hist_kernel<<<eb, thr>>>(ei, cnt, E);
    scan_kernel<<<1, 1024>>>(cnt, rowptr, ofs, N);
    scatter_kernel<<<eb, thr>>>(ei, ofs, srcs, dsts, eids, E);
    // 8-9: MP1
    copy_kernel<<<(n4 + 255) / 256, thr>>>((const float4*)h0, (float4*)h1, n4);
    edge_fused<<<gE, thr>>>(efr, wr + OM1 + 2 * FD * FD, bmp1, Xs, Xd, h1, E);
    // 10-12: MP2
    gemm_node<1><<<gN2, thr>>>(h1, wr + OM2, wr + OM2 + FD * FD, nullptr, nullptr, Xs, Xd, N, 0, 0);
    copy_kernel<<<(n4 + 255) / 256, thr>>>((const float4*)h1, (float4*)h0, n4);
    edge_fused<<<gE, thr>>>(efr, wr + OM2 + 2 * FD * FD, bmp2, Xs, Xd, h0, E);
    // 13: FFN2 + residual
    gemm_node<1><<<gN, thr>>>(h0, wr + OW2, nullptr, bff2, x, (float*)d_out, nullptr, N, 0, 0);
}

// round 8
// speedup vs baseline: 1.1741x; 1.1741x over previous
#include <cuda_runtime.h>
#include <mma.h>
#include <cstdint>
#include <cstddef>

using namespace nvcuda;

#define NN 10000
#define NE 320000
#define FD 256
#define EDF 64

// weight offsets inside g_wr
#define OW1 0
#define OM1 (FD * FD)
#define OM2 (OM1 + 576 * FD)
#define OW2 (OM2 + 576 * FD)
#define WTOT (OW2 + FD * FD)

// ---------------- scratch ----------------
__device__ float g_h0[NN * FD];
__device__ float g_h1[NN * FD];
__device__ float g_Xs[NN * FD];
__device__ float g_Xd[NN * FD];
__device__ float g_xr[NN * FD];
__device__ float g_efr[(size_t)NE * EDF];
__device__ float g_wr[WTOT];

__device__ __forceinline__ float gelu_f(float v) {
    float u = 0.7978845608028654f * (v + 0.044715f * v * v * v);
    float t;
    asm("tanh.approx.f32 %0, %1;" : "=f"(t) : "f"(u));
    return 0.5f * v * (1.0f + t);
}

__device__ __forceinline__ void cp16(uint32_t dst, const void* src, bool p) {
    asm volatile("cp.async.ca.shared.global [%0], [%1], 16, %2;"
                 :: "r"(dst), "l"(src), "r"(p ? 16 : 0));
}
#define CP_COMMIT() asm volatile("cp.async.commit_group;")
#define CP_WAIT(n)  asm volatile("cp.async.wait_group %0;" :: "n"(n))

// ---------------- tf32 pre-round: x, ef, all weights in ONE launch ----------------
__global__ void round_all(const float* __restrict__ x, const float* __restrict__ ef,
                          const float* __restrict__ wff1, const float* __restrict__ wmp1,
                          const float* __restrict__ wmp2, const float* __restrict__ wff2,
                          float* __restrict__ xr, float* __restrict__ efr,
                          float* __restrict__ wr) {
    const int NX4 = NN * FD / 4;
    const int NE4 = NE * EDF / 4;
    const int W14 = FD * FD / 4, WM4 = 576 * FD / 4;
    long long i = (long long)blockIdx.x * blockDim.x + threadIdx.x;
    const float4* s;
    float4* d;
    long long j = i;
    if (j < NX4) { s = (const float4*)x; d = (float4*)xr; }
    else {
        j -= NX4;
        if (j < NE4) { s = (const float4*)ef; d = (float4*)efr; }
        else {
            j -= NE4;
            if (j < W14) { s = (const float4*)wff1; d = (float4*)(wr + OW1); }
            else {
                j -= W14;
                if (j < WM4) { s = (const float4*)wmp1; d = (float4*)(wr + OM1); }
                else {
                    j -= WM4;
                    if (j < WM4) { s = (const float4*)wmp2; d = (float4*)(wr + OM2); }
                    else {
                        j -= WM4;
                        if (j >= W14) return;
                        s = (const float4*)wff2; d = (float4*)(wr + OW2);
                    }
                }
            }
        }
    }
    float4 v = s[j];
    v.x = wmma::__float_to_tf32(v.x);
    v.y = wmma::__float_to_tf32(v.y);
    v.z = wmma::__float_to_tf32(v.z);
    v.w = wmma::__float_to_tf32(v.w);
    d[j] = v;
}

__global__ void copy_kernel(const float4* __restrict__ a, float4* __restrict__ b, int n4) {
    int i = blockIdx.x * blockDim.x + threadIdx.x;
    if (i < n4) b[i] = a[i];
}

// ---------------- node GEMM: cp.async 2-stage, cvt-free when inputs pre-rounded ----------------
template <int CVT_A>
__global__ void __launch_bounds__(256) gemm_node(
    const float* __restrict__ A,
    const float* __restrict__ B0, const float* __restrict__ B1,
    const float* __restrict__ bias,
    const float* __restrict__ resid,
    float* __restrict__ C0, float* __restrict__ C1,
    float* __restrict__ Cdup,
    int M, int dogelu, int roundout)
{
    constexpr int BM = 128, BN = 64, BK = 32;
    constexpr int LDA = 36, LDB = 68;
    constexpr int STG = BM * LDA + BK * LDB;
    __shared__ __align__(16) float sm[2 * STG];
    float* Cs = sm;

    int tid = threadIdx.x;
    int warp = tid >> 5;
    int wm = warp >> 1, wn = warp & 1;
    int bm = blockIdx.x * BM;
    int sel = blockIdx.y >> 2;
    int cg = blockIdx.y & 3;
    const float* B = sel ? B1 : B0;
    float* C = sel ? C1 : C0;
    int bn = cg * BN;

    int lra = tid >> 3, lca = (tid & 7) << 2;
    int lrb = tid >> 4, lcb = (tid & 15) << 2;

    auto issue = [&](int st, int k0) {
        float* As = sm + st * STG;
        float* Bs = As + BM * LDA;
#pragma unroll
        for (int p = 0; p < 4; p++) {
            int row = lra + 32 * p;
            int grow = bm + row;
            cp16((uint32_t)__cvta_generic_to_shared(As + row * LDA + lca),
                 A + (size_t)grow * FD + k0 + lca, grow < M);
        }
#pragma unroll
        for (int p = 0; p < 2; p++) {
            int row = lrb + 16 * p;
            cp16((uint32_t)__cvta_generic_to_shared(Bs + row * LDB + lcb),
                 B + (size_t)(k0 + row) * FD + bn + lcb, true);
        }
    };

    wmma::fragment<wmma::accumulator, 16, 16, 8, float> acc[2][2];
#pragma unroll
    for (int i = 0; i < 2; i++)
#pragma unroll
        for (int j = 0; j < 2; j++) wmma::fill_fragment(acc[i][j], 0.0f);

    issue(0, 0);
    CP_COMMIT();

    constexpr int NIT = FD / BK;  // 8
#pragma unroll 1
    for (int it = 0; it < NIT; it++) {
        if (it + 1 < NIT) {
            issue((it + 1) & 1, (it + 1) * BK);
            CP_COMMIT();
            CP_WAIT(1);
        } else {
            CP_WAIT(0);
        }
        __syncthreads();
        float* As = sm + (it & 1) * STG;
        float* Bs = As + BM * LDA;
#pragma unroll
        for (int kk = 0; kk < BK; kk += 8) {
            wmma::fragment<wmma::matrix_a, 16, 16, 8, wmma::precision::tf32, wmma::row_major> a[2];
            wmma::fragment<wmma::matrix_b, 16, 16, 8, wmma::precision::tf32, wmma::row_major> b[2];
#pragma unroll
            for (int i = 0; i < 2; i++) {
                wmma::load_matrix_sync(a[i], As + (wm * 32 + i * 16) * LDA + kk, LDA);
                if (CVT_A) {
#pragma unroll
                    for (int e = 0; e < a[i].num_elements; e++)
                        a[i].x[e] = wmma::__float_to_tf32(a[i].x[e]);
                }
            }
#pragma unroll
            for (int j = 0; j < 2; j++)
                wmma::load_matrix_sync(b[j], Bs + kk * LDB + wn * 32 + j * 16, LDB);
#pragma unroll
            for (int i = 0; i < 2; i++)
#pragma unroll
                for (int j = 0; j < 2; j++)
                    wmma::mma_sync(acc[i][j], a[i], b[j], acc[i][j]);
        }
        __syncthreads();
    }

#pragma unroll
    for (int i = 0; i < 2; i++)
#pragma unroll
        for (int j = 0; j < 2; j++)
            wmma::store_matrix_sync(Cs + (wm * 32 + i * 16) * BN + wn * 32 + j * 16,
                                    acc[i][j], BN, wmma::mem_row_major);
    __syncthreads();
    for (int idx = tid; idx < BM * BN; idx += 256) {
        int r = idx >> 6, c = idx & 63;
        int grow = bm + r;
        if (grow >= M) continue;
        float v = Cs[idx];
        if (bias) v += bias[bn + c];
        if (dogelu) v = gelu_f(v);
        if (roundout) v = wmma::__float_to_tf32(v);
        if (resid) v += resid[(size_t)grow * FD + bn + c];
        C[(size_t)grow * FD + bn + c] = v;
        if (Cdup) Cdup[(size_t)grow * FD + bn + c] = v;
    }
}

// ---------------- direct-order fused edge kernel ----------------
// Block: 128 consecutive edges x 2 column groups. ef streamed coalesced via cp.async.
// m = gelu(ef[e] @ Wef[:,cols] + b + Xs[src] + Xd[dst]); atomicAdd into out[dst] (RED).
__global__ void __launch_bounds__(256) edge_direct(
    const float* __restrict__ ef,    // tf32-rounded
    const float* __restrict__ Wef,   // [64, 256] tf32-rounded
    const float* __restrict__ bias,
    const float* __restrict__ Xs, const float* __restrict__ Xd,
    const int* __restrict__ ei,      // src = ei[e], dst = ei[E+e]
    float* __restrict__ out,         // pre-seeded with hin
    int E)
{
    constexpr int CH = 128, LDA = 68, LDB = 68;
    __shared__ __align__(16) float Aef[CH * LDA];    // persists both cgs
    __shared__ __align__(16) float CsWb[CH * LDA];   // Wef tile, then C tile
    __shared__ int s_src[CH], s_dst[CH];

    int tid = threadIdx.x;
    int base = blockIdx.x * CH;
    int warp = tid >> 5;
    int wm = warp >> 1, wn = warp & 1;

    // ef tile: fully coalesced stream, async
#pragma unroll
    for (int p = 0; p < 8; p++) {
        int j = tid + 256 * p;
        int row = j >> 4;
        int c4 = j & 15;
        cp16((uint32_t)__cvta_generic_to_shared(Aef + row * LDA + c4 * 4),
             ef + (size_t)(base + row) * EDF + c4 * 4, base + row < E);
    }
    CP_COMMIT();

    // metadata (coalesced)
    if (tid < CH) {
        int e = base + tid;
        bool v = e < E;
        s_src[tid] = v ? ei[e] : 0;
        s_dst[tid] = v ? ei[E + e] : -1;
    }
    CP_WAIT(0);
    __syncthreads();

    int c = tid & 63;
    int q = tid >> 6;

#pragma unroll 1
    for (int cgi = 0; cgi < 2; cgi++) {
        int cg = blockIdx.y * 2 + cgi;
        float* Wb = CsWb;
#pragma unroll
        for (int p = 0; p < 4; p++) {
            int j = tid + 256 * p;
            int row = j >> 4;
            int c4 = j & 15;
            *(float4*)(Wb + row * LDB + c4 * 4) =
                *(const float4*)(Wef + (size_t)row * FD + cg * 64 + c4 * 4);
        }
        __syncthreads();

        wmma::fragment<wmma::accumulator, 16, 16, 8, float> acc[2][2];
#pragma unroll
        for (int i = 0; i < 2; i++)
#pragma unroll
            for (int j = 0; j < 2; j++) wmma::fill_fragment(acc[i][j], 0.0f);

#pragma unroll
        for (int kk = 0; kk < EDF; kk += 8) {
            wmma::fragment<wmma::matrix_a, 16, 16, 8, wmma::precision::tf32, wmma::row_major> a[2];
            wmma::fragment<wmma::matrix_b, 16, 16, 8, wmma::precision::tf32, wmma::row_major> b[2];
#pragma unroll
            for (int i = 0; i < 2; i++)
                wmma::load_matrix_sync(a[i], Aef + (wm * 32 + i * 16) * LDA + kk, LDA);
#pragma unroll
            for (int j = 0; j < 2; j++)
                wmma::load_matrix_sync(b[j], Wb + kk * LDB + wn * 32 + j * 16, LDB);
#pragma unroll
            for (int i = 0; i < 2; i++)
#pragma unroll
                for (int j = 0; j < 2; j++)
                    wmma::mma_sync(acc[i][j], a[i], b[j], acc[i][j]);
        }
        __syncthreads();  // Wb reads done

        float* Cs = CsWb;
#pragma unroll
        for (int i = 0; i < 2; i++)
#pragma unroll
            for (int j = 0; j < 2; j++)
                wmma::store_matrix_sync(Cs + (wm * 32 + i * 16) * LDA + wn * 32 + j * 16,
                                        acc[i][j], LDA, wmma::mem_row_major);
        __syncthreads();

        // epilogue: all loads batched & independent; atomics fire-and-forget (RED)
        float bv = bias[cg * 64 + c];
#pragma unroll
        for (int r0 = 0; r0 < 32; r0 += 8) {
            float xs[8], xd[8];
            int dd[8];
#pragma unroll
            for (int r = 0; r < 8; r++) {
                int row = q * 32 + r0 + r;
                int d = s_dst[row];
                dd[r] = d;
                xs[r] = Xs[(size_t)s_src[row] * FD + cg * 64 + c];
                xd[r] = (d >= 0) ? Xd[(size_t)d * FD + cg * 64 + c] : 0.0f;
            }
#pragma unroll
            for (int r = 0; r < 8; r++) {
                int row = q * 32 + r0 + r;
                if (dd[r] >= 0) {
                    float v = gelu_f(Cs[row * LDA + c] + bv + xs[r] + xd[r]);
                    atomicAdd(&out[(size_t)dd[r] * FD + cg * 64 + c], v);
                }
            }
        }
        __syncthreads();  // before next cg overwrites CsWb
    }
}

// ---------------- launch ----------------
extern "C" void kernel_launch(void* const* d_in, const int* in_sizes, int n_in,
                              void* d_out, int out_size) {
    const float* x    = (const float*)d_in[0];
    const int* ei     = (const int*)d_in[1];   // int32 (JAX x64 disabled)
    const float* ef   = (const float*)d_in[2];
    const float* Wff1 = (const float*)d_in[3];
    const float* bff1 = (const float*)d_in[4];
    const float* Wmp1 = (const float*)d_in[5];
    const float* bmp1 = (const float*)d_in[6];
    const float* Wmp2 = (const float*)d_in[7];
    const float* bmp2 = (const float*)d_in[8];
    const float* Wff2 = (const float*)d_in[9];
    const float* bff2 = (const float*)d_in[10];

    int N = in_sizes[0] / FD;
    int E = in_sizes[1] / 2;

    float *h0, *h1, *Xs, *Xd, *xr, *efr, *wr;
    cudaGetSymbolAddress((void**)&h0, g_h0);
    cudaGetSymbolAddress((void**)&h1, g_h1);
    cudaGetSymbolAddress((void**)&Xs, g_Xs);
    cudaGetSymbolAddress((void**)&Xd, g_Xd);
    cudaGetSymbolAddress((void**)&xr, g_xr);
    cudaGetSymbolAddress((void**)&efr, g_efr);
    cudaGetSymbolAddress((void**)&wr, g_wr);

    dim3 thr(256);
    int n4 = N * FD / 4;
    long long tot4 = (long long)N * FD / 4 + (long long)E * EDF / 4 + WTOT / 4;

    dim3 gN((N + 127) / 128, 4);
    dim3 gN2((N + 127) / 128, 8);
    dim3 gE((E + 127) / 128, 2);

    // 1: pre-round everything to tf32
    round_all<<<(int)((tot4 + 255) / 256), thr>>>(x, ef, Wff1, Wmp1, Wmp2, Wff2, xr, efr, wr);
    // 2: FFN1 -> h0, and dup-write h1 (seed for MP1 aggregation)
    gemm_node<0><<<gN, thr>>>(xr, wr + OW1, nullptr, bff1, nullptr, h0, nullptr, h1, N, 1, 1);
    // 3: dual1 -> Xs, Xd
    gemm_node<0><<<gN2, thr>>>(h0, wr + OM1, wr + OM1 + FD * FD, nullptr, nullptr, Xs, Xd, nullptr, N, 0, 0);
    // 4: edge1 (ncu PROBE) -> h1 += agg
    edge_direct<<<gE, thr>>>(efr, wr + OM1 + 2 * FD * FD, bmp1, Xs, Xd, ei, h1, E);
    // 5: dual2 -> Xs, Xd (h1 has fp32 atomics -> cvt A in-kernel)
    gemm_node<1><<<gN2, thr>>>(h1, wr + OM2, wr + OM2 + FD * FD, nullptr, nullptr, Xs, Xd, nullptr, N, 0, 0);
    // 6: seed h0 = h1
    copy_kernel<<<(n4 + 255) / 256, thr>>>((const float4*)h1, (float4*)h0, n4);
    // 7: edge2 -> h0 += agg
    edge_direct<<<gE, thr>>>(efr, wr + OM2 + 2 * FD * FD, bmp2, Xs, Xd, ei, h0, E);
    // 8: FFN2 + residual -> out
    gemm_node<1><<<gN, thr>>>(h0, wr + OW2, nullptr, bff2, x, (float*)d_out, nullptr, nullptr, N, 0, 0);
}